// round 2
// baseline (speedup 1.0000x reference)
#include <cuda_runtime.h>
#include <cuda_fp16.h>
#include <mma.h>

using namespace nvcuda;

#define N_ATOMS  100000
#define N_PAIRS  1600000

// ---------------- scratch (device globals; no allocation allowed) ----------
__device__ float  g_u  [N_ATOMS * 50];
__device__ float  g_v  [N_ATOMS * 50];
__device__ float  g_AA [N_ATOMS * 50];
__device__ float  g_PA [N_ATOMS * 50];
__device__ __half g_PP [(size_t)N_PAIRS * 50];

__device__ __forceinline__ float frelu(float x) { return fmaxf(x, 0.f); }

// ============================================================================
// K1: per-atom GEMM.  X = af(64x80pad) @ W(80x160)  -> AA|u|v.  Zero g_PA.
// ============================================================================
struct K1S {
    __half Af[64 * 80];
    __half Wt[80 * 160];
    float  C [64 * 160];
};

__global__ __launch_bounds__(256) void k1_atoms(
    const float* __restrict__ af,
    const float* __restrict__ W_AA, const float* __restrict__ b_AA,
    const float* __restrict__ W_AP)
{
    extern __shared__ char smem_raw[];
    K1S& S = *reinterpret_cast<K1S*>(smem_raw);
    const int tid  = threadIdx.x;
    const int base = blockIdx.x * 64;

    for (int idx = tid; idx < 80 * 160; idx += 256) {
        int d = idx / 160, n = idx - d * 160;
        float w = 0.f;
        if (d < 75) {
            if      (n < 50)  w = W_AA[d * 50 + n];
            else if (n < 100) w = W_AP[d * 50 + (n - 50)];
            else if (n < 150) w = W_AP[(75 + d) * 50 + (n - 100)];
        }
        S.Wt[idx] = __float2half(w);
    }
    for (int idx = tid; idx < 64 * 80; idx += 256) {
        int m = idx / 80, d = idx - m * 80;
        int ga = base + m;
        float v = (ga < N_ATOMS && d < 75) ? af[(size_t)ga * 75 + d] : 0.f;
        S.Af[idx] = __float2half(v);
    }
    // zero PA accumulator for this block's atoms
    for (int idx = tid; idx < 64 * 50; idx += 256) {
        int ga = base + idx / 50;
        if (ga < N_ATOMS) g_PA[(size_t)ga * 50 + (idx % 50)] = 0.f;
    }
    __syncthreads();

    const int warp = tid >> 5;
    for (int t = warp; t < 40; t += 8) {           // 4 m-tiles x 10 n-tiles
        int mt = t / 10, nt = t % 10;
        wmma::fragment<wmma::accumulator, 16, 16, 16, float> c;
        wmma::fill_fragment(c, 0.f);
        for (int k = 0; k < 5; k++) {
            wmma::fragment<wmma::matrix_a, 16, 16, 16, __half, wmma::row_major> a;
            wmma::fragment<wmma::matrix_b, 16, 16, 16, __half, wmma::row_major> b;
            wmma::load_matrix_sync(a, S.Af + mt * 16 * 80 + k * 16, 80);
            wmma::load_matrix_sync(b, S.Wt + k * 16 * 160 + nt * 16, 160);
            wmma::mma_sync(c, a, b, c);
        }
        wmma::store_matrix_sync(S.C + mt * 16 * 160 + nt * 16, c, 160, wmma::mem_row_major);
    }
    __syncthreads();

    for (int idx = tid; idx < 64 * 160; idx += 256) {
        int m = idx / 160, n = idx - m * 160;
        int ga = base + m;
        if (ga >= N_ATOMS || n >= 150) continue;
        float cv = S.C[idx];
        if (n < 50)       g_AA[(size_t)ga * 50 + n]        = frelu(cv + __ldg(b_AA + n));
        else if (n < 100) g_u [(size_t)ga * 50 + (n - 50)] = cv;
        else              g_v [(size_t)ga * 50 + (n - 100)]= cv;
    }
}

// ============================================================================
// K2a: pair front GEMM.  pf(128x16pad) @ [W_PA|W_PP](16x112pad).
//      PP -> g_PP (fp16).  PA -> relu, run-compressed atomicAdd into g_PA.
// ============================================================================
struct K2aS {
    __half Pf[128 * 16];
    __half Wc[16 * 112];
    float  C [128 * 112];
    float  bb[112];           // 0..49 b_PA | 50..99 b_PP
    int    seg[128];
};

__global__ __launch_bounds__(256) void k2a_pairfront(
    const float* __restrict__ pf,
    const int*   __restrict__ pair_split,
    const float* __restrict__ W_PA, const float* __restrict__ b_PA,
    const float* __restrict__ W_PP, const float* __restrict__ b_PP)
{
    extern __shared__ char smem_raw[];
    K2aS& S = *reinterpret_cast<K2aS*>(smem_raw);
    const int tid  = threadIdx.x;
    const int base = blockIdx.x * 128;          // N_PAIRS % 128 == 0

    for (int idx = tid; idx < 128 * 16; idx += 256) {
        int p = idx / 16, d = idx - p * 16;
        float v = (d < 14) ? pf[(size_t)(base + p) * 14 + d] : 0.f;
        S.Pf[idx] = __float2half(v);
    }
    for (int idx = tid; idx < 16 * 112; idx += 256) {
        int d = idx / 112, n = idx - d * 112;
        float w = 0.f;
        if (d < 14 && n < 100)
            w = (n < 50) ? W_PA[d * 50 + n] : W_PP[d * 50 + (n - 50)];
        S.Wc[idx] = __float2half(w);
    }
    if (tid < 112) S.bb[tid] = (tid < 50) ? b_PA[tid] : (tid < 100 ? b_PP[tid - 50] : 0.f);
    if (tid < 128) S.seg[tid] = pair_split[base + tid];
    __syncthreads();

    const int warp = tid >> 5;
    for (int t = warp; t < 56; t += 8) {          // 8 m-tiles x 7 n-tiles, K=1 tile
        int mt = t % 8, nt = t / 8;
        wmma::fragment<wmma::accumulator, 16, 16, 16, float> c;
        wmma::fill_fragment(c, 0.f);
        wmma::fragment<wmma::matrix_a, 16, 16, 16, __half, wmma::row_major> a;
        wmma::fragment<wmma::matrix_b, 16, 16, 16, __half, wmma::row_major> b;
        wmma::load_matrix_sync(a, S.Pf + mt * 16 * 16, 16);
        wmma::load_matrix_sync(b, S.Wc + nt * 16, 112);
        wmma::mma_sync(c, a, b, c);
        wmma::store_matrix_sync(S.C + mt * 16 * 112 + nt * 16, c, 112, wmma::mem_row_major);
    }
    __syncthreads();

    // PP out (fp16)
    for (int idx = tid; idx < 128 * 50; idx += 256) {
        int p = idx / 50, n = idx - p * 50;
        float v = frelu(S.C[p * 112 + 50 + n] + S.bb[50 + n]);
        g_PP[(size_t)(base + p) * 50 + n] = __float2half(v);
    }
    // PA segmented reduction (pair_split sorted -> long runs)
    {
        int col   = tid & 63;
        int chunk = tid >> 6;                    // 0..3, 32 rows each
        if (col < 50) {
            int r0 = chunk * 32;
            float acc = 0.f;
            int cur = S.seg[r0];
            for (int r = r0; r < r0 + 32; r++) {
                int sg = S.seg[r];
                float v = frelu(S.C[r * 112 + col] + S.bb[col]);
                if (sg != cur) {
                    atomicAdd(&g_PA[(size_t)cur * 50 + col], acc);
                    acc = 0.f; cur = sg;
                }
                acc += v;
            }
            atomicAdd(&g_PA[(size_t)cur * 50 + col], acc);
        }
    }
}

// ============================================================================
// K2b: main pair GEMM.  T=[s|PP] (256x112 fp16) @ W_P (112x64pad) -> P.
//      s built from L2-resident u/v gathers.
// ============================================================================
struct K2bS {
    __half T [256 * 112];
    __half Wp[112 * 64];
    float  C [256 * 64];
    float  bAP[64];
    float  bP [64];
    int    ii[256];
    int    jj[256];
};

__global__ __launch_bounds__(256) void k2b_pairmain(
    const int*   __restrict__ atom_to_pair,
    const float* __restrict__ W_P, const float* __restrict__ b_P,
    const float* __restrict__ b_AP,
    float* __restrict__ outP)
{
    extern __shared__ char smem_raw[];
    K2bS& S = *reinterpret_cast<K2bS*>(smem_raw);
    const int tid  = threadIdx.x;
    const int base = blockIdx.x * 256;          // N_PAIRS % 256 == 0

    S.ii[tid] = atom_to_pair[2 * (size_t)(base + tid)];
    S.jj[tid] = atom_to_pair[2 * (size_t)(base + tid) + 1];
    if (tid < 64) {
        S.bAP[tid] = (tid < 50) ? b_AP[tid] : 0.f;
        S.bP [tid] = (tid < 50) ? b_P [tid] : 0.f;
    }
    for (int idx = tid; idx < 112 * 64; idx += 256) {
        int k = idx / 64, n = idx - k * 64;
        float w = (k < 100 && n < 50) ? W_P[k * 50 + n] : 0.f;
        S.Wp[idx] = __float2half(w);
    }
    __syncthreads();

    // thread p builds its T row
    {
        const int p = tid;
        const int i = S.ii[p], j = S.jj[p];
        const float2* ui = (const float2*)(g_u + (size_t)i * 50);
        const float2* vi = (const float2*)(g_v + (size_t)i * 50);
        const float2* uj = (const float2*)(g_u + (size_t)j * 50);
        const float2* vj = (const float2*)(g_v + (size_t)j * 50);
        const float2* bb = (const float2*)S.bAP;
        __half2* Ts = (__half2*)(S.T + p * 112);
        #pragma unroll 5
        for (int q = 0; q < 25; q++) {
            float2 a1 = __ldg(ui + q), a2 = __ldg(vj + q);
            float2 a3 = __ldg(uj + q), a4 = __ldg(vi + q);
            float2 b2 = bb[q];
            float slo = frelu(a1.x + a2.x + b2.x) + frelu(a3.x + a4.x + b2.x);
            float shi = frelu(a1.y + a2.y + b2.y) + frelu(a3.y + a4.y + b2.y);
            Ts[q] = __floats2half2_rn(slo, shi);
        }
        const __half2* pp = (const __half2*)(g_PP + (size_t)(base + p) * 50);
        __half2* Tp = (__half2*)(S.T + p * 112 + 50);
        #pragma unroll 5
        for (int q = 0; q < 25; q++) Tp[q] = __ldg(pp + q);
        __half2* Tz = (__half2*)(S.T + p * 112 + 100);
        #pragma unroll
        for (int q = 0; q < 6; q++) Tz[q] = __floats2half2_rn(0.f, 0.f);
    }
    __syncthreads();

    const int warp = tid >> 5;
    for (int t = warp; t < 64; t += 8) {          // 16 m-tiles x 4 n-tiles
        int mt = t / 4, nt = t % 4;
        wmma::fragment<wmma::accumulator, 16, 16, 16, float> c;
        wmma::fill_fragment(c, 0.f);
        #pragma unroll
        for (int k = 0; k < 7; k++) {
            wmma::fragment<wmma::matrix_a, 16, 16, 16, __half, wmma::row_major> a;
            wmma::fragment<wmma::matrix_b, 16, 16, 16, __half, wmma::row_major> b;
            wmma::load_matrix_sync(a, S.T + mt * 16 * 112 + k * 16, 112);
            wmma::load_matrix_sync(b, S.Wp + k * 16 * 64 + nt * 16, 64);
            wmma::mma_sync(c, a, b, c);
        }
        wmma::store_matrix_sync(S.C + mt * 16 * 64 + nt * 16, c, 64, wmma::mem_row_major);
    }
    __syncthreads();

    for (int idx = tid; idx < 256 * 50; idx += 256) {
        int p = idx / 50, n = idx - p * 50;
        outP[(size_t)(base + p) * 50 + n] = frelu(S.C[p * 64 + n] + S.bP[n]);
    }
}

// ============================================================================
// K3: atom output GEMM.  [AA|PA](128x112pad) @ W_A(112x64pad) -> A.
// ============================================================================
struct K3S {
    __half X[128 * 112];
    __half W[112 * 64];
    float  C[128 * 64];
    float  bA[64];
};

__global__ __launch_bounds__(256) void k3_atomsout(
    const float* __restrict__ W_A, const float* __restrict__ b_A,
    float* __restrict__ outA)
{
    extern __shared__ char smem_raw[];
    K3S& S = *reinterpret_cast<K3S*>(smem_raw);
    const int tid  = threadIdx.x;
    const int base = blockIdx.x * 128;

    for (int idx = tid; idx < 128 * 112; idx += 256) {
        int m = idx / 112, k = idx - m * 112;
        int ga = base + m;
        float v = 0.f;
        if (ga < N_ATOMS) {
            if      (k < 50)  v = g_AA[(size_t)ga * 50 + k];
            else if (k < 100) v = g_PA[(size_t)ga * 50 + (k - 50)];
        }
        S.X[idx] = __float2half(v);
    }
    for (int idx = tid; idx < 112 * 64; idx += 256) {
        int k = idx / 64, n = idx - k * 64;
        float w = (k < 100 && n < 50) ? W_A[k * 50 + n] : 0.f;
        S.W[idx] = __float2half(w);
    }
    if (tid < 64) S.bA[tid] = (tid < 50) ? b_A[tid] : 0.f;
    __syncthreads();

    const int warp = tid >> 5;
    for (int t = warp; t < 32; t += 8) {          // 8 m-tiles x 4 n-tiles
        int mt = t % 8, nt = t / 8;
        wmma::fragment<wmma::accumulator, 16, 16, 16, float> c;
        wmma::fill_fragment(c, 0.f);
        #pragma unroll
        for (int k = 0; k < 7; k++) {
            wmma::fragment<wmma::matrix_a, 16, 16, 16, __half, wmma::row_major> a;
            wmma::fragment<wmma::matrix_b, 16, 16, 16, __half, wmma::row_major> b;
            wmma::load_matrix_sync(a, S.X + mt * 16 * 112 + k * 16, 112);
            wmma::load_matrix_sync(b, S.W + k * 16 * 64 + nt * 16, 64);
            wmma::mma_sync(c, a, b, c);
        }
        wmma::store_matrix_sync(S.C + mt * 16 * 64 + nt * 16, c, 64, wmma::mem_row_major);
    }
    __syncthreads();

    for (int idx = tid; idx < 128 * 50; idx += 256) {
        int m = idx / 50, n = idx - m * 50;
        int ga = base + m;
        if (ga < N_ATOMS)
            outA[(size_t)ga * 50 + n] = frelu(S.C[m * 64 + n] + S.bA[n]);
    }
}

// ============================================================================
extern "C" void kernel_launch(void* const* d_in, const int* in_sizes, int n_in,
                              void* d_out, int out_size) {
    const float* atom_features = (const float*)d_in[0];
    const float* pair_features = (const float*)d_in[1];
    const int*   pair_split    = (const int*)  d_in[2];
    const int*   atom_to_pair  = (const int*)  d_in[3];
    const float* W_AA = (const float*)d_in[4];
    const float* b_AA = (const float*)d_in[5];
    const float* W_PA = (const float*)d_in[6];
    const float* b_PA = (const float*)d_in[7];
    const float* W_A  = (const float*)d_in[8];
    const float* b_A  = (const float*)d_in[9];
    const float* W_AP = (const float*)d_in[10];
    const float* b_AP = (const float*)d_in[11];
    const float* W_PP = (const float*)d_in[12];
    const float* b_PP = (const float*)d_in[13];
    const float* W_P  = (const float*)d_in[14];
    const float* b_P  = (const float*)d_in[15];

    float* outA = (float*)d_out;                        // [100000, 50]
    float* outP = (float*)d_out + (size_t)N_ATOMS * 50; // [1600000, 50]

    cudaFuncSetAttribute(k1_atoms,     cudaFuncAttributeMaxDynamicSharedMemorySize, (int)sizeof(K1S));
    cudaFuncSetAttribute(k2a_pairfront,cudaFuncAttributeMaxDynamicSharedMemorySize, (int)sizeof(K2aS));
    cudaFuncSetAttribute(k2b_pairmain, cudaFuncAttributeMaxDynamicSharedMemorySize, (int)sizeof(K2bS));
    cudaFuncSetAttribute(k3_atomsout,  cudaFuncAttributeMaxDynamicSharedMemorySize, (int)sizeof(K3S));

    k1_atoms<<<(N_ATOMS + 63) / 64, 256, sizeof(K1S)>>>(atom_features, W_AA, b_AA, W_AP);
    k2a_pairfront<<<N_PAIRS / 128, 256, sizeof(K2aS)>>>(pair_features, pair_split,
                                                        W_PA, b_PA, W_PP, b_PP);
    k2b_pairmain<<<N_PAIRS / 256, 256, sizeof(K2bS)>>>(atom_to_pair, W_P, b_P, b_AP, outP);
    k3_atomsout<<<(N_ATOMS + 127) / 128, 256, sizeof(K3S)>>>(W_A, b_A, outA);
}

// round 3
// speedup vs baseline: 2.2426x; 2.2426x over previous
#include <cuda_runtime.h>
#include <cuda_fp16.h>
#include <mma.h>

using namespace nvcuda;

#define N_ATOMS  100000
#define N_PAIRS  1600000

// ---------------- scratch (device globals; no allocation allowed) ----------
// g_uv interleaved: g_uv[atom*100 + 2k] = u_k, [atom*100 + 2k + 1] = v_k  (fp16, 20MB)
__device__ __half g_uv [(size_t)N_ATOMS * 100];
__device__ float  g_AA [(size_t)N_ATOMS * 50];
__device__ float  g_PA [(size_t)N_ATOMS * 50];

__device__ __forceinline__ float frelu(float x) { return fmaxf(x, 0.f); }

// ============================================================================
// K1: per-atom GEMM. X = af(128x80pad) @ W(80x160) -> AA | u | v.  Zero g_PA.
// 512 threads, 2 blocks/SM.  Warp w: m-tile w>>1, n-tiles (w&1)*5 .. +4.
// ============================================================================
struct K1S {
    union {
        struct { __half Af[128 * 80]; __half Wt[80 * 160]; };
        float C[128 * 160];
    };
    float bAA[64];
};

__global__ __launch_bounds__(512) void k1_atoms(
    const float* __restrict__ af,
    const float* __restrict__ W_AA, const float* __restrict__ b_AA,
    const float* __restrict__ W_AP)
{
    extern __shared__ char smem_raw[];
    K1S& S = *reinterpret_cast<K1S*>(smem_raw);
    const int tid  = threadIdx.x;
    const int base = blockIdx.x * 128;

    for (int idx = tid; idx < 80 * 160; idx += 512) {
        int d = idx / 160, n = idx - d * 160;
        float w = 0.f;
        if (d < 75) {
            if      (n < 50)  w = W_AA[d * 50 + n];
            else if (n < 100) w = W_AP[d * 50 + (n - 50)];
            else if (n < 150) w = W_AP[(75 + d) * 50 + (n - 100)];
        }
        S.Wt[idx] = __float2half(w);
    }
    for (int idx = tid; idx < 128 * 80; idx += 512) {
        int m = idx / 80, d = idx - m * 80;
        int ga = base + m;
        float v = (ga < N_ATOMS && d < 75) ? af[(size_t)ga * 75 + d] : 0.f;
        S.Af[idx] = __float2half(v);
    }
    if (tid < 50) S.bAA[tid] = b_AA[tid];
    // zero PA accumulator for this block's atoms
    for (int idx = tid; idx < 128 * 50; idx += 512) {
        int ga = base + idx / 50;
        if (ga < N_ATOMS) g_PA[(size_t)ga * 50 + (idx % 50)] = 0.f;
    }
    __syncthreads();

    const int warp = tid >> 5;
    const int mt = warp >> 1;
    const int nb = (warp & 1) * 5;

    wmma::fragment<wmma::accumulator, 16, 16, 16, float> acc[5];
    #pragma unroll
    for (int q = 0; q < 5; q++) wmma::fill_fragment(acc[q], 0.f);
    #pragma unroll
    for (int k = 0; k < 5; k++) {
        wmma::fragment<wmma::matrix_a, 16, 16, 16, __half, wmma::row_major> a;
        wmma::load_matrix_sync(a, S.Af + mt * 16 * 80 + k * 16, 80);
        #pragma unroll
        for (int q = 0; q < 5; q++) {
            wmma::fragment<wmma::matrix_b, 16, 16, 16, __half, wmma::row_major> b;
            wmma::load_matrix_sync(b, S.Wt + k * 16 * 160 + (nb + q) * 16, 160);
            wmma::mma_sync(acc[q], a, b, acc[q]);
        }
    }
    __syncthreads();                   // all reads of Af/Wt done before C overwrite
    #pragma unroll
    for (int q = 0; q < 5; q++)
        wmma::store_matrix_sync(S.C + mt * 16 * 160 + (nb + q) * 16, acc[q], 160,
                                wmma::mem_row_major);
    __syncthreads();

    // AA -> f32 global ; (u,v) -> interleaved fp16
    for (int idx = tid; idx < 128 * 50; idx += 512) {
        int m = idx / 50, n = idx - m * 50;
        int ga = base + m;
        if (ga >= N_ATOMS) continue;
        g_AA[(size_t)ga * 50 + n] = frelu(S.C[m * 160 + n] + S.bAA[n]);
        float u = S.C[m * 160 + 50 + n];
        float v = S.C[m * 160 + 100 + n];
        ((__half2*)g_uv)[(size_t)ga * 50 + n] = __floats2half2_rn(u, v);
    }
}

// ============================================================================
// K2: fused pair kernel. 256 pairs/block, 512 threads, 2 blocks/SM.
//  Phase G : s[k]=relu(u_i+v_j+b)+relu(u_j+v_i+b) -> T cols 0..49 (coalesced
//            half2 gathers from L2-resident g_uv, 16 threads/pair)
//  Phase A : SIMT f32: PP=relu(pf@W_PP+b) -> T cols 50..99,
//            PA=relu(pf@W_PA+b) -> run-compressed segmented atomicAdd(g_PA)
//  Phase M : T(256x112 fp16) @ W_P(112x64pad) via wmma, C unioned over T
//  Phase E : outP = relu(C + b_P)
// ============================================================================
struct K2S {
    union {
        __half T[256 * 112];
        float  C[256 * 64];
    };
    __half Wp [112 * 64];
    float  pf [256 * 14];
    float  Wpa[14 * 52];
    float  Wpp[14 * 52];
    float  bAP[64], bPA[64], bPP[64], bP[64];
    int    ii[256], jj[256], seg[256];
};

__global__ __launch_bounds__(512) void k2_pairs(
    const float* __restrict__ pair_features,
    const int*   __restrict__ pair_split,
    const int*   __restrict__ atom_to_pair,
    const float* __restrict__ W_PA, const float* __restrict__ b_PA,
    const float* __restrict__ W_PP, const float* __restrict__ b_PP,
    const float* __restrict__ W_P,  const float* __restrict__ b_P,
    const float* __restrict__ b_AP,
    float* __restrict__ outP)
{
    extern __shared__ char smem_raw[];
    K2S& S = *reinterpret_cast<K2S*>(smem_raw);
    const int tid  = threadIdx.x;
    const int base = blockIdx.x * 256;           // N_PAIRS % 256 == 0

    // ---- stage ----
    for (int idx = tid; idx < 256 * 14; idx += 512)
        S.pf[idx] = pair_features[(size_t)base * 14 + idx];
    for (int idx = tid; idx < 112 * 64; idx += 512) {
        int k = idx / 64, n = idx - k * 64;
        float w = (k < 100 && n < 50) ? W_P[k * 50 + n] : 0.f;
        S.Wp[idx] = __float2half(w);
    }
    for (int idx = tid; idx < 14 * 52; idx += 512) {
        int d = idx / 52, n = idx - d * 52;
        S.Wpa[idx] = (n < 50) ? W_PA[d * 50 + n] : 0.f;
        S.Wpp[idx] = (n < 50) ? W_PP[d * 50 + n] : 0.f;
    }
    if (tid < 64) {
        S.bAP[tid] = (tid < 50) ? b_AP[tid] : 0.f;
        S.bPA[tid] = (tid < 50) ? b_PA[tid] : 0.f;
        S.bPP[tid] = (tid < 50) ? b_PP[tid] : 0.f;
        S.bP [tid] = (tid < 50) ? b_P [tid] : 0.f;
    }
    if (tid < 256) {
        int2 p2 = ((const int2*)atom_to_pair)[base + tid];
        S.ii[tid] = p2.x;
        S.jj[tid] = p2.y;
        S.seg[tid] = pair_split[base + tid];
    }
    // zero-pad T cols 100..111
    for (int idx = tid; idx < 256 * 6; idx += 512) {
        int p = idx / 6, q = idx - p * 6;
        ((__half2*)(S.T + p * 112 + 100))[q] = __floats2half2_rn(0.f, 0.f);
    }
    __syncthreads();

    // ---- Phase G: symmetrized AP -> T[:,0:50]  (16 threads per pair) ----
    {
        const int t = tid & 15;
        #pragma unroll
        for (int pass = 0; pass < 8; pass++) {
            const int p = pass * 32 + (tid >> 4);
            const int i = S.ii[p], j = S.jj[p];
            const __half2* ri = (const __half2*)g_uv + (size_t)i * 50;
            const __half2* rj = (const __half2*)g_uv + (size_t)j * 50;
            #pragma unroll
            for (int q = 0; q < 3; q++) {
                int k = t + q * 16;
                __half2 a = __ldg(ri + k), b = __ldg(rj + k);
                float ui = __low2float(a), vi = __high2float(a);
                float uj = __low2float(b), vj = __high2float(b);
                float bb = S.bAP[k];
                S.T[p * 112 + k] =
                    __float2half(frelu(ui + vj + bb) + frelu(uj + vi + bb));
            }
            if (t < 2) {
                int k = 48 + t;
                __half2 a = __ldg(ri + k), b = __ldg(rj + k);
                float ui = __low2float(a), vi = __high2float(a);
                float uj = __low2float(b), vj = __high2float(b);
                float bb = S.bAP[k];
                S.T[p * 112 + k] =
                    __float2half(frelu(ui + vj + bb) + frelu(uj + vi + bb));
            }
        }
    }

    // ---- Phase A: SIMT PP -> T[:,50:100], PA -> segmented atomics ----
    if (tid < 400) {
        const int col = tid % 50, chunk = tid / 50;    // 8 chunks x 32 rows
        float wpa[14], wpp[14];
        #pragma unroll
        for (int d = 0; d < 14; d++) {
            wpa[d] = S.Wpa[d * 52 + col];
            wpp[d] = S.Wpp[d * 52 + col];
        }
        const float bpa = S.bPA[col], bpp = S.bPP[col];
        const int r0 = chunk * 32;
        float acc = 0.f;
        int cur = S.seg[r0];
        for (int r = r0; r < r0 + 32; r++) {
            const float* pfr = &S.pf[r * 14];
            float sa = bpa, sp = bpp;
            #pragma unroll
            for (int d = 0; d < 14; d++) {
                float x = pfr[d];
                sa += x * wpa[d];
                sp += x * wpp[d];
            }
            S.T[r * 112 + 50 + col] = __float2half(frelu(sp));
            int sg = S.seg[r];
            if (sg != cur) {
                atomicAdd(&g_PA[(size_t)cur * 50 + col], acc);
                acc = 0.f; cur = sg;
            }
            acc += frelu(sa);
        }
        atomicAdd(&g_PA[(size_t)cur * 50 + col], acc);
    }
    __syncthreads();

    // ---- Phase M: T @ Wp, warp w -> m-tile w, n-tiles 0..3, K=7 ----
    {
        const int mt = tid >> 5;
        wmma::fragment<wmma::accumulator, 16, 16, 16, float> acc[4];
        #pragma unroll
        for (int q = 0; q < 4; q++) wmma::fill_fragment(acc[q], 0.f);
        #pragma unroll
        for (int k = 0; k < 7; k++) {
            wmma::fragment<wmma::matrix_a, 16, 16, 16, __half, wmma::row_major> a;
            wmma::load_matrix_sync(a, S.T + mt * 16 * 112 + k * 16, 112);
            #pragma unroll
            for (int q = 0; q < 4; q++) {
                wmma::fragment<wmma::matrix_b, 16, 16, 16, __half, wmma::row_major> b;
                wmma::load_matrix_sync(b, S.Wp + k * 16 * 64 + q * 16, 64);
                wmma::mma_sync(acc[q], a, b, acc[q]);
            }
        }
        __syncthreads();               // all T reads done before C overwrite
        #pragma unroll
        for (int q = 0; q < 4; q++)
            wmma::store_matrix_sync(S.C + mt * 16 * 64 + q * 16, acc[q], 64,
                                    wmma::mem_row_major);
    }
    __syncthreads();

    // ---- Phase E: epilogue ----
    for (int idx = tid; idx < 256 * 50; idx += 512) {
        int p = idx / 50, n = idx - p * 50;
        outP[(size_t)(base + p) * 50 + n] = frelu(S.C[p * 64 + n] + S.bP[n]);
    }
}

// ============================================================================
// K3: atom output GEMM. [AA|PA](256x112pad) @ W_A(112x64pad) -> A.
// 512 threads, 2 blocks/SM.  Warp w: m-tile w, n-tiles 0..3.
// ============================================================================
struct K3S {
    union {
        __half X[256 * 112];
        float  C[256 * 64];
    };
    __half W[112 * 64];
    float  bA[64];
};

__global__ __launch_bounds__(512) void k3_atomsout(
    const float* __restrict__ W_A, const float* __restrict__ b_A,
    float* __restrict__ outA)
{
    extern __shared__ char smem_raw[];
    K3S& S = *reinterpret_cast<K3S*>(smem_raw);
    const int tid  = threadIdx.x;
    const int base = blockIdx.x * 256;

    for (int idx = tid; idx < 256 * 112; idx += 512) {
        int m = idx / 112, k = idx - m * 112;
        int ga = base + m;
        float v = 0.f;
        if (ga < N_ATOMS) {
            if      (k < 50)  v = g_AA[(size_t)ga * 50 + k];
            else if (k < 100) v = g_PA[(size_t)ga * 50 + (k - 50)];
        }
        S.X[idx] = __float2half(v);
    }
    for (int idx = tid; idx < 112 * 64; idx += 512) {
        int k = idx / 64, n = idx - k * 64;
        float w = (k < 100 && n < 50) ? W_A[k * 50 + n] : 0.f;
        S.W[idx] = __float2half(w);
    }
    if (tid < 64) S.bA[tid] = (tid < 50) ? b_A[tid] : 0.f;
    __syncthreads();

    {
        const int mt = tid >> 5;
        wmma::fragment<wmma::accumulator, 16, 16, 16, float> acc[4];
        #pragma unroll
        for (int q = 0; q < 4; q++) wmma::fill_fragment(acc[q], 0.f);
        #pragma unroll
        for (int k = 0; k < 7; k++) {
            wmma::fragment<wmma::matrix_a, 16, 16, 16, __half, wmma::row_major> a;
            wmma::load_matrix_sync(a, S.X + mt * 16 * 112 + k * 16, 112);
            #pragma unroll
            for (int q = 0; q < 4; q++) {
                wmma::fragment<wmma::matrix_b, 16, 16, 16, __half, wmma::row_major> b;
                wmma::load_matrix_sync(b, S.W + k * 16 * 64 + q * 16, 64);
                wmma::mma_sync(acc[q], a, b, acc[q]);
            }
        }
        __syncthreads();
        #pragma unroll
        for (int q = 0; q < 4; q++)
            wmma::store_matrix_sync(S.C + mt * 16 * 64 + q * 16, acc[q], 64,
                                    wmma::mem_row_major);
    }
    __syncthreads();

    for (int idx = tid; idx < 256 * 50; idx += 512) {
        int m = idx / 50, n = idx - m * 50;
        int ga = base + m;
        if (ga < N_ATOMS)
            outA[(size_t)ga * 50 + n] = frelu(S.C[m * 64 + n] + S.bA[n]);
    }
}

// ============================================================================
extern "C" void kernel_launch(void* const* d_in, const int* in_sizes, int n_in,
                              void* d_out, int out_size) {
    const float* atom_features = (const float*)d_in[0];
    const float* pair_features = (const float*)d_in[1];
    const int*   pair_split    = (const int*)  d_in[2];
    const int*   atom_to_pair  = (const int*)  d_in[3];
    const float* W_AA = (const float*)d_in[4];
    const float* b_AA = (const float*)d_in[5];
    const float* W_PA = (const float*)d_in[6];
    const float* b_PA = (const float*)d_in[7];
    const float* W_A  = (const float*)d_in[8];
    const float* b_A  = (const float*)d_in[9];
    const float* W_AP = (const float*)d_in[10];
    const float* b_AP = (const float*)d_in[11];
    const float* W_PP = (const float*)d_in[12];
    const float* b_PP = (const float*)d_in[13];
    const float* W_P  = (const float*)d_in[14];
    const float* b_P  = (const float*)d_in[15];

    float* outA = (float*)d_out;                        // [100000, 50]
    float* outP = (float*)d_out + (size_t)N_ATOMS * 50; // [1600000, 50]

    cudaFuncSetAttribute(k1_atoms,    cudaFuncAttributeMaxDynamicSharedMemorySize, (int)sizeof(K1S));
    cudaFuncSetAttribute(k2_pairs,    cudaFuncAttributeMaxDynamicSharedMemorySize, (int)sizeof(K2S));
    cudaFuncSetAttribute(k3_atomsout, cudaFuncAttributeMaxDynamicSharedMemorySize, (int)sizeof(K3S));

    k1_atoms<<<(N_ATOMS + 127) / 128, 512, sizeof(K1S)>>>(atom_features, W_AA, b_AA, W_AP);
    k2_pairs<<<N_PAIRS / 256, 512, sizeof(K2S)>>>(pair_features, pair_split, atom_to_pair,
                                                  W_PA, b_PA, W_PP, b_PP, W_P, b_P, b_AP, outP);
    k3_atomsout<<<(N_ATOMS + 255) / 256, 512, sizeof(K3S)>>>(W_A, b_A, outA);
}